// round 3
// baseline (speedup 1.0000x reference)
#include <cuda_runtime.h>
#include <math.h>

// Problem shape (fixed by the dataset): B=16, N=1024, E=128, kv row = 2E+1 = 257
#define BATCH   16
#define NATOMS  1024
#define EDIM    128
#define KVROW   257
#define TI      128
#define TJ      128
#define THREADS 256

#define SMEM_K      (EDIM * (TI + 1))
#define SMEM_V      (EDIM * (TJ + 1))
#define SMEM_FLOATS (SMEM_K + SMEM_V + 3 * TJ + 8)
#define SMEM_BYTES  (SMEM_FLOATS * sizeof(float))

// One block per (batch, 128-row i-tile). K tile resident in SMEM (transposed,
// mask and 1/sqrt(E) folded), loop over 8 V tiles of 128 j-rows each.
// Each thread owns an 8x8 register tile of S (rows ty+16r, cols tx+16c),
// then fuses the position-weighting epilogue and accumulates 3 action
// components per row. Final reduction over the 16 column-threads via
// half-warp shuffles; tanh/scale/mask applied at writeout.
__global__ __launch_bounds__(THREADS, 1)
void gen_actions_kernel(const float* __restrict__ kv,
                        const float* __restrict__ pos,
                        const float* __restrict__ mask,
                        const float* __restrict__ ascale,
                        float* __restrict__ out)
{
    extern __shared__ float sm[];
    float* sK   = sm;                   // [EDIM][TI+1]  k^T, mask*invsqrtE folded
    float* sV   = sK + SMEM_K;          // [EDIM][TJ+1]  v^T, mask folded
    float* sP   = sV + SMEM_V;          // x[0,128) y[128,256) z[256,384)
    float* sRed = sP + 3 * TJ;          // 8 warp partials for mask sum

    const int tid = threadIdx.x;
    const int tx  = tid & 15;
    const int ty  = tid >> 4;
    const int b   = blockIdx.y;
    const int i0  = blockIdx.x * TI;

    const float* kvb = kv   + (size_t)b * NATOMS * KVROW;
    const float* mb  = mask + (size_t)b * NATOMS;
    const float* pb  = pos  + (size_t)b * NATOMS * 3;

    const float inv_sqrt_e = 0.088388347648318447f;  // 1/sqrt(128)

    // ---- load K tile transposed (coalesced along e; stride-129 rows ->
    //      conflict-free STS since 129 % 32 == 1) ----
    for (int idx = tid; idx < TI * EDIM; idx += THREADS) {
        int i = idx >> 7;            // 0..127
        int e = idx & (EDIM - 1);
        float m = mb[i0 + i];
        sK[e * (TI + 1) + i] = kvb[(size_t)(i0 + i) * KVROW + e] * (m * inv_sqrt_e);
    }

    // ---- mask sum for this batch (denominator) ----
    {
        float ms = 0.f;
        for (int n = tid; n < NATOMS; n += THREADS) ms += mb[n];
        #pragma unroll
        for (int off = 16; off > 0; off >>= 1)
            ms += __shfl_xor_sync(0xFFFFFFFFu, ms, off);
        if ((tid & 31) == 0) sRed[tid >> 5] = ms;
    }
    __syncthreads();

    float msum = 0.f;
    #pragma unroll
    for (int w = 0; w < THREADS / 32; w++) msum += sRed[w];
    const float inv_msum = 1.0f / msum;
    const float as = ascale[0];

    // ---- this thread's 8 row positions (fixed for whole block) ----
    float pix[8], piy[8], piz[8];
    #pragma unroll
    for (int r = 0; r < 8; r++) {
        int gi = i0 + ty + 16 * r;
        const float* p = pb + (size_t)gi * 3;
        pix[r] = p[0]; piy[r] = p[1]; piz[r] = p[2];
    }

    float accx[8], accy[8], accz[8];
    #pragma unroll
    for (int r = 0; r < 8; r++) { accx[r] = 0.f; accy[r] = 0.f; accz[r] = 0.f; }

    for (int jt = 0; jt < NATOMS; jt += TJ) {
        __syncthreads();   // previous tile's GEMM finished reading sV

        // V tile transposed + this tile's positions
        for (int idx = tid; idx < TJ * EDIM; idx += THREADS) {
            int j = idx >> 7;
            int e = idx & (EDIM - 1);
            float m = mb[jt + j];
            sV[e * (TJ + 1) + j] = kvb[(size_t)(jt + j) * KVROW + EDIM + e] * m;
        }
        if (tid < TJ) {
            const float* p = pb + (size_t)(jt + tid) * 3;
            sP[tid] = p[0]; sP[TJ + tid] = p[1]; sP[2 * TJ + tid] = p[2];
        }
        __syncthreads();

        // column positions for this thread's 8 j-columns
        float pjx[8], pjy[8], pjz[8];
        #pragma unroll
        for (int c = 0; c < 8; c++) {
            int jj = tx + 16 * c;
            pjx[c] = sP[jj]; pjy[c] = sP[TJ + jj]; pjz[c] = sP[2 * TJ + jj];
        }

        // ---- S = k_i . v_j  (8x8 register tile, FFMA-bound mainloop) ----
        float S[8][8];
        #pragma unroll
        for (int r = 0; r < 8; r++)
            #pragma unroll
            for (int c = 0; c < 8; c++) S[r][c] = 0.f;

        #pragma unroll 4
        for (int ks = 0; ks < EDIM; ks++) {
            const float* kr = sK + ks * (TI + 1);
            const float* vr = sV + ks * (TJ + 1);
            float kf[8], vf[8];
            #pragma unroll
            for (int r = 0; r < 8; r++) kf[r] = kr[ty + 16 * r];  // 2-addr bcast
            #pragma unroll
            for (int c = 0; c < 8; c++) vf[c] = vr[tx + 16 * c];  // conflict-free
            #pragma unroll
            for (int r = 0; r < 8; r++)
                #pragma unroll
                for (int c = 0; c < 8; c++)
                    S[r][c] = fmaf(kf[r], vf[c], S[r][c]);
        }

        // ---- fused epilogue: acc += S/|p_i - p_j| * (p_i - p_j) ----
        #pragma unroll
        for (int c = 0; c < 8; c++) {
            float qx = pjx[c], qy = pjy[c], qz = pjz[c];
            #pragma unroll
            for (int r = 0; r < 8; r++) {
                float dx = pix[r] - qx;
                float dy = piy[r] - qy;
                float dz = piz[r] - qz;
                float d2 = fmaf(dx, dx, fmaf(dy, dy, dz * dz));
                // diagonal (d2==0): fmax clamp -> huge finite inv, dx==0 -> 0
                float inv = rsqrtf(fmaxf(d2, 1e-36f));
                float w = S[r][c] * inv;
                accx[r] = fmaf(w, dx, accx[r]);
                accy[r] = fmaf(w, dy, accy[r]);
                accz[r] = fmaf(w, dz, accz[r]);
            }
        }
    }

    // ---- reduce across the 16 column-threads (half-warp xor shuffles) ----
    #pragma unroll
    for (int off = 1; off < 16; off <<= 1) {
        #pragma unroll
        for (int r = 0; r < 8; r++) {
            accx[r] += __shfl_xor_sync(0xFFFFFFFFu, accx[r], off);
            accy[r] += __shfl_xor_sync(0xFFFFFFFFu, accy[r], off);
            accz[r] += __shfl_xor_sync(0xFFFFFFFFu, accz[r], off);
        }
    }

    if (tx == 0) {
        #pragma unroll
        for (int r = 0; r < 8; r++) {
            int gi = i0 + ty + 16 * r;
            float s = as * mb[gi];
            float* o = out + ((size_t)b * NATOMS + gi) * 3;
            o[0] = tanhf(accx[r] * inv_msum) * s;
            o[1] = tanhf(accy[r] * inv_msum) * s;
            o[2] = tanhf(accz[r] * inv_msum) * s;
        }
    }
}

extern "C" void kernel_launch(void* const* d_in, const int* in_sizes, int n_in,
                              void* d_out, int out_size) {
    const float* kv   = (const float*)d_in[0];
    const float* pos  = (const float*)d_in[1];
    const float* mask = (const float*)d_in[2];
    const float* asc  = (const float*)d_in[3];
    float* out = (float*)d_out;

    // ~133.7 KB dynamic smem -> needs opt-in above the 48KB default.
    // Not a stream op; safe under graph capture, idempotent, deterministic.
    cudaFuncSetAttribute(gen_actions_kernel,
                         cudaFuncAttributeMaxDynamicSharedMemorySize,
                         (int)SMEM_BYTES);

    dim3 grid(NATOMS / TI, BATCH);   // 8 x 16 = 128 blocks
    gen_actions_kernel<<<grid, THREADS, SMEM_BYTES>>>(kv, pos, mask, asc, out);
}

// round 4
// speedup vs baseline: 1.0758x; 1.0758x over previous
#include <cuda_runtime.h>
#include <math.h>

// Shape fixed by dataset: B=16, N=1024, E=128, kv row = 2E+1 = 257
#define BATCH   16
#define NATOMS  1024
#define EDIM    128
#define KVROW   257
#define TI      128
#define TJ      128
#define THREADS 256

// SMEM layout (floats):
//  sK  : [128 ksteps][129 pairs]  K dup'd (k,k) as f32x2, row stride 258 floats
//  sV  : [128 ksteps][65 pairs]   V packed (v_j, v_{j+64}),  row stride 130 floats
//  sPn : negated j-tile positions  x[0,128) y[128,256) z[256,384)
//  sPi : dup'd i positions, ull per (i,axis): float off i*6 + axis*2
//  sRed: 8 warp partials
#define SK_STRIDE 258
#define SV_STRIDE 130
#define OFF_SV  (EDIM * SK_STRIDE)                  // 33024
#define OFF_PN  (OFF_SV + EDIM * SV_STRIDE)         // +16640
#define OFF_PI  (OFF_PN + 3 * TJ)                   // +384
#define OFF_RED (OFF_PI + TI * 6)                   // +768
#define SMEM_FLOATS (OFF_RED + 8)
#define SMEM_BYTES  (SMEM_FLOATS * sizeof(float))   // ~203.3 KB

typedef unsigned long long ull;

__device__ __forceinline__ ull pk2(float lo, float hi) {
    ull r; asm("mov.b64 %0, {%1, %2};" : "=l"(r) : "f"(lo), "f"(hi)); return r;
}
__device__ __forceinline__ void upk2(ull v, float& lo, float& hi) {
    asm("mov.b64 {%0, %1}, %2;" : "=f"(lo), "=f"(hi) : "l"(v));
}
__device__ __forceinline__ ull fma2(ull a, ull b, ull c) {
    ull d; asm("fma.rn.f32x2 %0, %1, %2, %3;" : "=l"(d) : "l"(a), "l"(b), "l"(c)); return d;
}
__device__ __forceinline__ ull add2(ull a, ull b) {
    ull d; asm("add.rn.f32x2 %0, %1, %2;" : "=l"(d) : "l"(a), "l"(b)); return d;
}
__device__ __forceinline__ ull mul2(ull a, ull b) {
    ull d; asm("mul.rn.f32x2 %0, %1, %2;" : "=l"(d) : "l"(a), "l"(b)); return d;
}

__global__ __launch_bounds__(THREADS, 1)
void gen_actions_kernel(const float* __restrict__ kv,
                        const float* __restrict__ pos,
                        const float* __restrict__ mask,
                        const float* __restrict__ ascale,
                        float* __restrict__ out)
{
    extern __shared__ float sm[];
    float* sK   = sm;
    float* sV   = sm + OFF_SV;
    float* sPn  = sm + OFF_PN;
    float* sPi  = sm + OFF_PI;
    float* sRed = sm + OFF_RED;

    const int tid = threadIdx.x;
    const int tx  = tid & 15;          // 16 column-thread groups
    const int ty  = tid >> 4;          // 16 row-thread groups
    const int b   = blockIdx.y;
    const int i0  = blockIdx.x * TI;

    const float* kvb = kv   + (size_t)b * NATOMS * KVROW;
    const float* mb  = mask + (size_t)b * NATOMS;
    const float* pb  = pos  + (size_t)b * NATOMS * 3;

    const float inv_sqrt_e = 0.088388347648318447f;  // 1/sqrt(128)

    // ---- K tile: dup-packed (k,k) f32x2, mask*invsqrtE folded.
    //      gmem coalesced (consecutive tid -> consecutive e). One-time cost.
    for (int idx = tid; idx < TI * EDIM; idx += THREADS) {
        int i = idx >> 7;
        int e = idx & (EDIM - 1);
        float v = kvb[(size_t)(i0 + i) * KVROW + e] * (mb[i0 + i] * inv_sqrt_e);
        *(ull*)&sK[e * SK_STRIDE + 2 * i] = pk2(v, v);
    }

    // ---- i positions, dup-packed once per block ----
    if (tid < TI) {
        const float* p = pb + (size_t)(i0 + tid) * 3;
        *(ull*)&sPi[tid * 6 + 0] = pk2(p[0], p[0]);
        *(ull*)&sPi[tid * 6 + 2] = pk2(p[1], p[1]);
        *(ull*)&sPi[tid * 6 + 4] = pk2(p[2], p[2]);
    }

    // ---- mask sum ----
    {
        float ms = 0.f;
        for (int n = tid; n < NATOMS; n += THREADS) ms += mb[n];
        #pragma unroll
        for (int off = 16; off > 0; off >>= 1)
            ms += __shfl_xor_sync(0xFFFFFFFFu, ms, off);
        if ((tid & 31) == 0) sRed[tid >> 5] = ms;
    }
    __syncthreads();

    float msum = 0.f;
    #pragma unroll
    for (int w = 0; w < THREADS / 32; w++) msum += sRed[w];
    const float inv_msum = 1.0f / msum;
    const float as = ascale[0];

    // packed accumulators: lane0 sums j-cols [0,64) of each tile, lane1 sums [64,128)
    ull accx[8], accy[8], accz[8];
    #pragma unroll
    for (int r = 0; r < 8; r++) { accx[r] = 0ULL; accy[r] = 0ULL; accz[r] = 0ULL; }

    for (int jt = 0; jt < NATOMS; jt += TJ) {
        __syncthreads();   // prior tile fully consumed (S regs + sPn reads done)

        // V tile: packed pairs (j, j+64); gmem coalesced; mask folded.
        for (int idx = tid; idx < TJ * EDIM; idx += THREADS) {
            int j = idx >> 7;
            int e = idx & (EDIM - 1);
            float v = kvb[(size_t)(jt + j) * KVROW + EDIM + e] * mb[jt + j];
            sV[e * SV_STRIDE + 2 * (j & 63) + (j >> 6)] = v;
        }
        // negated j positions
        if (tid < TJ) {
            const float* p = pb + (size_t)(jt + tid) * 3;
            sPn[tid] = -p[0]; sPn[TJ + tid] = -p[1]; sPn[2 * TJ + tid] = -p[2];
        }
        __syncthreads();

        // packed negated column positions for this thread's 4 column-pairs
        ull nqx[4], nqy[4], nqz[4];
        #pragma unroll
        for (int c = 0; c < 4; c++) {
            int p = tx + 16 * c;
            nqx[c] = pk2(sPn[p],          sPn[p + 64]);
            nqy[c] = pk2(sPn[TJ + p],     sPn[TJ + p + 64]);
            nqz[c] = pk2(sPn[2 * TJ + p], sPn[2 * TJ + p + 64]);
        }

        // ---- packed GEMM: S[r][c] = pair-dot(k_row, v_colpair) ----
        ull S[8][4];
        #pragma unroll
        for (int r = 0; r < 8; r++)
            #pragma unroll
            for (int c = 0; c < 4; c++) S[r][c] = 0ULL;

        #pragma unroll 2
        for (int ks = 0; ks < EDIM; ks++) {
            const float* kr = sK + ks * SK_STRIDE;
            const float* vr = sV + ks * SV_STRIDE;
            ull kf[8], vf[4];
            #pragma unroll
            for (int r = 0; r < 8; r++)
                kf[r] = *(const ull*)&kr[2 * (ty + 16 * r)];   // broadcast
            #pragma unroll
            for (int c = 0; c < 4; c++)
                vf[c] = *(const ull*)&vr[2 * (tx + 16 * c)];   // conflict-free
            #pragma unroll
            for (int r = 0; r < 8; r++)
                #pragma unroll
                for (int c = 0; c < 4; c++)
                    S[r][c] = fma2(kf[r], vf[c], S[r][c]);
        }

        // ---- packed epilogue: acc += S * (p_i - p_j)/|p_i - p_j| ----
        #pragma unroll
        for (int r = 0; r < 8; r++) {
            int ii = ty + 16 * r;
            ull pix2 = *(const ull*)&sPi[ii * 6 + 0];
            ull piy2 = *(const ull*)&sPi[ii * 6 + 2];
            ull piz2 = *(const ull*)&sPi[ii * 6 + 4];
            #pragma unroll
            for (int c = 0; c < 4; c++) {
                ull dx2 = add2(pix2, nqx[c]);
                ull dy2 = add2(piy2, nqy[c]);
                ull dz2 = add2(piz2, nqz[c]);
                ull d2  = mul2(dz2, dz2);
                d2 = fma2(dy2, dy2, d2);
                d2 = fma2(dx2, dx2, d2);
                float dlo, dhi;
                upk2(d2, dlo, dhi);
                // diagonal (d2==0): clamp -> huge finite inv, dx==0 -> contributes 0
                float ilo = rsqrtf(fmaxf(dlo, 1e-36f));
                float ihi = rsqrtf(fmaxf(dhi, 1e-36f));
                ull w2 = mul2(S[r][c], pk2(ilo, ihi));
                accx[r] = fma2(w2, dx2, accx[r]);
                accy[r] = fma2(w2, dy2, accy[r]);
                accz[r] = fma2(w2, dz2, accz[r]);
            }
        }
    }

    // ---- fold packed halves, reduce across 16 column-threads ----
    float ax[8], ay[8], az[8];
    #pragma unroll
    for (int r = 0; r < 8; r++) {
        float lo, hi;
        upk2(accx[r], lo, hi); ax[r] = lo + hi;
        upk2(accy[r], lo, hi); ay[r] = lo + hi;
        upk2(accz[r], lo, hi); az[r] = lo + hi;
    }
    #pragma unroll
    for (int off = 1; off < 16; off <<= 1) {
        #pragma unroll
        for (int r = 0; r < 8; r++) {
            ax[r] += __shfl_xor_sync(0xFFFFFFFFu, ax[r], off);
            ay[r] += __shfl_xor_sync(0xFFFFFFFFu, ay[r], off);
            az[r] += __shfl_xor_sync(0xFFFFFFFFu, az[r], off);
        }
    }

    if (tx == 0) {
        #pragma unroll
        for (int r = 0; r < 8; r++) {
            int gi = i0 + ty + 16 * r;
            float s = as * mb[gi];
            float* o = out + ((size_t)b * NATOMS + gi) * 3;
            o[0] = tanhf(ax[r] * inv_msum) * s;
            o[1] = tanhf(ay[r] * inv_msum) * s;
            o[2] = tanhf(az[r] * inv_msum) * s;
        }
    }
}

extern "C" void kernel_launch(void* const* d_in, const int* in_sizes, int n_in,
                              void* d_out, int out_size) {
    const float* kv   = (const float*)d_in[0];
    const float* pos  = (const float*)d_in[1];
    const float* mask = (const float*)d_in[2];
    const float* asc  = (const float*)d_in[3];
    float* out = (float*)d_out;

    cudaFuncSetAttribute(gen_actions_kernel,
                         cudaFuncAttributeMaxDynamicSharedMemorySize,
                         (int)SMEM_BYTES);

    dim3 grid(NATOMS / TI, BATCH);   // 8 x 16 = 128 blocks, one wave
    gen_actions_kernel<<<grid, THREADS, SMEM_BYTES>>>(kv, pos, mask, asc, out);
}